// round 1
// baseline (speedup 1.0000x reference)
#include <cuda_runtime.h>
#include <cstddef>

// mRoPE: q[T, 32*128], k[T, 8*128], cos/sin[3, T, 64].
// half = 64; sections (32,32,32) -> offs<32 uses plane 0, offs in [32,64) uses plane 1.
// out[j]    = x[j]*c[j]   - x[j+64]*s[j]
// out[j+64] = x[j+64]*c[j] + x[j]*s[j]
// q_out at d_out[0 .. T*4096), k_out at d_out[T*4096 ..).

#define T_TOK 16384
#define NQH   32
#define NKH   8
#define HS    128
#define HALF  64

__global__ __launch_bounds__(256, 4)
void mrope_kernel(const float* __restrict__ q,
                  const float* __restrict__ k,
                  const float* __restrict__ cosp,
                  const float* __restrict__ sinp,
                  float* __restrict__ qo,
                  float* __restrict__ ko)
{
    __shared__ float sc[HALF];
    __shared__ float ss[HALF];

    const int t   = blockIdx.x;
    const int tid = threadIdx.x;

    // Stage the per-token cos/sin rows (section select baked in).
    if (tid < HALF) {
        const int sec = (tid < 32) ? 0 : 1;
        sc[tid] = cosp[(size_t)sec * T_TOK * HALF + (size_t)t * HALF + tid];
    } else if (tid < 2 * HALF) {
        const int j   = tid - HALF;
        const int sec = (j < 32) ? 0 : 1;
        ss[j] = sinp[(size_t)sec * T_TOK * HALF + (size_t)t * HALF + j];
    }
    __syncthreads();

    const size_t qbase = (size_t)t * (NQH * HS);
    const size_t kbase = (size_t)t * (NKH * HS);

    // 16 float4-pair units per head, 40 heads -> 640 units per token.
    const int UNITS = (NQH + NKH) * (HALF / 4);

    for (int i = tid; i < UNITS; i += 256) {
        const int h  = i >> 4;       // head index 0..39
        const int j4 = i & 15;       // float4 index within half (0..15)

        const float* src;
        float*       dst;
        size_t       off;
        if (h < NQH) {
            src = q;  dst = qo;
            off = qbase + (size_t)h * HS + (size_t)j4 * 4;
        } else {
            src = k;  dst = ko;
            off = kbase + (size_t)(h - NQH) * HS + (size_t)j4 * 4;
        }

        const float4 a = *reinterpret_cast<const float4*>(src + off);         // x1
        const float4 b = *reinterpret_cast<const float4*>(src + off + HALF);  // x2
        const float4 c = *reinterpret_cast<const float4*>(&sc[j4 * 4]);
        const float4 s = *reinterpret_cast<const float4*>(&ss[j4 * 4]);

        float4 o1, o2;
        o1.x = fmaf(a.x, c.x, -b.x * s.x);
        o1.y = fmaf(a.y, c.y, -b.y * s.y);
        o1.z = fmaf(a.z, c.z, -b.z * s.z);
        o1.w = fmaf(a.w, c.w, -b.w * s.w);
        o2.x = fmaf(b.x, c.x,  a.x * s.x);
        o2.y = fmaf(b.y, c.y,  a.y * s.y);
        o2.z = fmaf(b.z, c.z,  a.z * s.z);
        o2.w = fmaf(b.w, c.w,  a.w * s.w);

        *reinterpret_cast<float4*>(dst + off)        = o1;
        *reinterpret_cast<float4*>(dst + off + HALF) = o2;
    }
}

extern "C" void kernel_launch(void* const* d_in, const int* in_sizes, int n_in,
                              void* d_out, int out_size)
{
    const float* q    = (const float*)d_in[0];
    const float* k    = (const float*)d_in[1];
    const float* cosp = (const float*)d_in[2];
    const float* sinp = (const float*)d_in[3];

    float* qo = (float*)d_out;
    float* ko = qo + (size_t)T_TOK * NQH * HS;

    mrope_kernel<<<T_TOK, 256>>>(q, k, cosp, sinp, qo, ko);
}

// round 3
// speedup vs baseline: 1.0794x; 1.0794x over previous
#include <cuda_runtime.h>
#include <cstddef>

// mRoPE flat elementwise version.
// q[T, 32*128], k[T, 8*128], cos/sin[3, T, 64]; half = 64.
// sections (32,32,32): offs<32 -> plane 0, offs in [32,64) -> plane 1.
// out[j]    = x[j]*c[j]   - x[j+64]*s[j]
// out[j+64] = x[j+64]*c[j] + x[j]*s[j]
//
// Unit = one float4 pair (j4-th float4 of a head's first half + matching
// float4 of the second half). One unit per thread, no smem, no barriers,
// no per-thread branches (q/k split at block granularity).

#define T_TOK 16384
#define HALF  64
#define NQH   32
#define NKH   8
#define HS    128

// q: 16 units/head * 32 heads = 512 units/token -> t = i>>9
// k: 16 units/head *  8 heads = 128 units/token -> t = i>>7
#define Q_UNITS (T_TOK * NQH * (HALF / 4))   // 8,388,608
#define K_UNITS (T_TOK * NKH * (HALF / 4))   // 2,097,152
#define Q_BLOCKS (Q_UNITS / 256)             // 32768
#define K_BLOCKS (K_UNITS / 256)             // 8192

__device__ __forceinline__ void rope_unit(const float* __restrict__ src,
                                          float* __restrict__ dst,
                                          const float* __restrict__ cosp,
                                          const float* __restrict__ sinp,
                                          size_t off, int t, int j4)
{
    // float4 at j4*4: entirely inside one section (boundary 32 == j4==8).
    const int sec = j4 >> 3;
    const size_t cs_off = (size_t)sec * (T_TOK * HALF) + (size_t)t * HALF + j4 * 4;

    const float4 a = *reinterpret_cast<const float4*>(src + off);         // x1
    const float4 b = *reinterpret_cast<const float4*>(src + off + HALF);  // x2
    const float4 c = *reinterpret_cast<const float4*>(cosp + cs_off);
    const float4 s = *reinterpret_cast<const float4*>(sinp + cs_off);

    float4 o1, o2;
    o1.x = fmaf(a.x, c.x, -b.x * s.x);
    o1.y = fmaf(a.y, c.y, -b.y * s.y);
    o1.z = fmaf(a.z, c.z, -b.z * s.z);
    o1.w = fmaf(a.w, c.w, -b.w * s.w);
    o2.x = fmaf(b.x, c.x,  a.x * s.x);
    o2.y = fmaf(b.y, c.y,  a.y * s.y);
    o2.z = fmaf(b.z, c.z,  a.z * s.z);
    o2.w = fmaf(b.w, c.w,  a.w * s.w);

    *reinterpret_cast<float4*>(dst + off)        = o1;
    *reinterpret_cast<float4*>(dst + off + HALF) = o2;
}

__global__ __launch_bounds__(256)
void mrope_flat_kernel(const float* __restrict__ q,
                       const float* __restrict__ k,
                       const float* __restrict__ cosp,
                       const float* __restrict__ sinp,
                       float* __restrict__ qo,
                       float* __restrict__ ko)
{
    const int bid = blockIdx.x;
    const int tid = threadIdx.x;

    if (bid < Q_BLOCKS) {
        const int i  = (bid << 8) + tid;     // q unit index
        const int t  = i >> 9;               // / 512
        const int r  = i & 511;
        const int j4 = r & 15;
        const size_t off = ((size_t)t << 12) + ((size_t)(r >> 4) << 7) + (j4 << 2);
        rope_unit(q, qo, cosp, sinp, off, t, j4);
    } else {
        const int i  = ((bid - Q_BLOCKS) << 8) + tid;  // k unit index
        const int t  = i >> 7;               // / 128
        const int r  = i & 127;
        const int j4 = r & 15;
        const size_t off = ((size_t)t << 10) + ((size_t)(r >> 4) << 7) + (j4 << 2);
        rope_unit(k, ko, cosp, sinp, off, t, j4);
    }
}

extern "C" void kernel_launch(void* const* d_in, const int* in_sizes, int n_in,
                              void* d_out, int out_size)
{
    const float* q    = (const float*)d_in[0];
    const float* k    = (const float*)d_in[1];
    const float* cosp = (const float*)d_in[2];
    const float* sinp = (const float*)d_in[3];

    float* qo = (float*)d_out;
    float* ko = qo + (size_t)T_TOK * NQH * HS;

    mrope_flat_kernel<<<Q_BLOCKS + K_BLOCKS, 256>>>(q, k, cosp, sinp, qo, ko);
}

// round 4
// speedup vs baseline: 1.1013x; 1.0203x over previous
#include <cuda_runtime.h>
#include <cstddef>

// mRoPE flat elementwise, 2 units/thread, front-batched loads, streaming hints.
// q[T, 32*128], k[T, 8*128], cos/sin[3, T, 64]; half = 64.
// sections (32,32,32): j<32 -> plane 0, j in [32,64) -> plane 1.
// out[j]    = x[j]*c[j]   - x[j+64]*s[j]
// out[j+64] = x[j+64]*c[j] + x[j]*s[j]

#define T_TOK 16384
#define HALF  64
#define NQH   32
#define NKH   8
#define HS    128

#define Q_UNITS (T_TOK * NQH * (HALF / 4))   // 8,388,608
#define K_UNITS (T_TOK * NKH * (HALF / 4))   // 2,097,152
#define Q_BLOCKS (Q_UNITS / 512)             // 16384  (512 units per block)
#define K_BLOCKS (K_UNITS / 512)             // 4096

struct UnitAddr {
    size_t off;     // element offset into src/dst
    size_t cs_off;  // element offset into cos/sin
};

__device__ __forceinline__ UnitAddr decode_q(int i)
{
    const int t  = i >> 9;            // 512 units per token
    const int r  = i & 511;
    const int j4 = r & 15;
    UnitAddr u;
    u.off    = ((size_t)t << 12) + ((size_t)(r >> 4) << 7) + (j4 << 2);
    u.cs_off = (size_t)(j4 >> 3) * (T_TOK * HALF) + ((size_t)t << 6) + (j4 << 2);
    return u;
}

__device__ __forceinline__ UnitAddr decode_k(int i)
{
    const int t  = i >> 7;            // 128 units per token
    const int r  = i & 127;
    const int j4 = r & 15;
    UnitAddr u;
    u.off    = ((size_t)t << 10) + ((size_t)(r >> 4) << 7) + (j4 << 2);
    u.cs_off = (size_t)(j4 >> 3) * (T_TOK * HALF) + ((size_t)t << 6) + (j4 << 2);
    return u;
}

__device__ __forceinline__ void rope_math(const float4& a, const float4& b,
                                          const float4& c, const float4& s,
                                          float4& o1, float4& o2)
{
    o1.x = fmaf(a.x, c.x, -b.x * s.x);
    o1.y = fmaf(a.y, c.y, -b.y * s.y);
    o1.z = fmaf(a.z, c.z, -b.z * s.z);
    o1.w = fmaf(a.w, c.w, -b.w * s.w);
    o2.x = fmaf(b.x, c.x,  a.x * s.x);
    o2.y = fmaf(b.y, c.y,  a.y * s.y);
    o2.z = fmaf(b.z, c.z,  a.z * s.z);
    o2.w = fmaf(b.w, c.w,  a.w * s.w);
}

__device__ __forceinline__ void rope_pair(const float* __restrict__ src,
                                          float* __restrict__ dst,
                                          const float* __restrict__ cosp,
                                          const float* __restrict__ sinp,
                                          UnitAddr u0, UnitAddr u1)
{
    // Front-batch all 8 loads (independent -> high MLP).
    const float4 a0 = __ldcs(reinterpret_cast<const float4*>(src + u0.off));
    const float4 b0 = __ldcs(reinterpret_cast<const float4*>(src + u0.off + HALF));
    const float4 a1 = __ldcs(reinterpret_cast<const float4*>(src + u1.off));
    const float4 b1 = __ldcs(reinterpret_cast<const float4*>(src + u1.off + HALF));
    const float4 c0 = __ldg (reinterpret_cast<const float4*>(cosp + u0.cs_off));
    const float4 s0 = __ldg (reinterpret_cast<const float4*>(sinp + u0.cs_off));
    const float4 c1 = __ldg (reinterpret_cast<const float4*>(cosp + u1.cs_off));
    const float4 s1 = __ldg (reinterpret_cast<const float4*>(sinp + u1.cs_off));

    float4 o1a, o2a, o1b, o2b;
    rope_math(a0, b0, c0, s0, o1a, o2a);
    rope_math(a1, b1, c1, s1, o1b, o2b);

    __stcs(reinterpret_cast<float4*>(dst + u0.off),        o1a);
    __stcs(reinterpret_cast<float4*>(dst + u0.off + HALF), o2a);
    __stcs(reinterpret_cast<float4*>(dst + u1.off),        o1b);
    __stcs(reinterpret_cast<float4*>(dst + u1.off + HALF), o2b);
}

__global__ __launch_bounds__(256)
void mrope_flat2_kernel(const float* __restrict__ q,
                        const float* __restrict__ k,
                        const float* __restrict__ cosp,
                        const float* __restrict__ sinp,
                        float* __restrict__ qo,
                        float* __restrict__ ko)
{
    const int bid = blockIdx.x;
    const int tid = threadIdx.x;

    if (bid < Q_BLOCKS) {
        const int base = bid << 9;           // 512 units per block
        rope_pair(q, qo, cosp, sinp,
                  decode_q(base + tid), decode_q(base + 256 + tid));
    } else {
        const int base = (bid - Q_BLOCKS) << 9;
        rope_pair(k, ko, cosp, sinp,
                  decode_k(base + tid), decode_k(base + 256 + tid));
    }
}

extern "C" void kernel_launch(void* const* d_in, const int* in_sizes, int n_in,
                              void* d_out, int out_size)
{
    const float* q    = (const float*)d_in[0];
    const float* k    = (const float*)d_in[1];
    const float* cosp = (const float*)d_in[2];
    const float* sinp = (const float*)d_in[3];

    float* qo = (float*)d_out;
    float* ko = qo + (size_t)T_TOK * NQH * HS;

    mrope_flat2_kernel<<<Q_BLOCKS + K_BLOCKS, 256>>>(q, k, cosp, sinp, qo, ko);
}